// round 11
// baseline (speedup 1.0000x reference)
#include <cuda_runtime.h>
#include <cuda_bf16.h>

#define BATCH 256
#define PPAIR 1024
#define TPTS  100
#define NGRID 65536
#define NB    (TPTS + 1)   // mid-buckets 0..100
#define NBINS (2 * NB)
#define SENT  (-1e30f)
#define CHUNK 4096         // floats per streamed chunk (16KB)
#define NCHUNK (NGRID / CHUNK)
#define SMEM_BYTES 63488

__device__ __forceinline__ void top2_upd(float v, float& a1, float& a2) {
    a2 = fmaxf(a2, fminf(a1, v));
    a1 = fmaxf(a1, v);
}
__device__ __forceinline__ float2 top2_merge(float2 a, float2 b) {
    float lo = fminf(a.x, b.x);
    return make_float2(fmaxf(a.x, b.x), fmaxf(lo, fmaxf(a.y, b.y)));
}

__global__ __launch_bounds__(1024, 2)
void pl_kernel(const float* __restrict__ inputs,
               const int*   __restrict__ dim_idx,
               const int*   __restrict__ birth_loc,
               const int*   __restrict__ death_loc,
               float* __restrict__ land,    // [B, 2, T, 2]
               float* __restrict__ trange)  // [B, 4]
{
    extern __shared__ unsigned char sraw[];
    float*    s_buf    = (float*)sraw;                        // 2*CHUNK = 32KB
    float2*   s_pr     = (float2*)(sraw + 32768);             // 1024    =  8KB
    float2 (*s_scan)[128] = (float2 (*)[128])(sraw + 40960);  // 4*128   =  4KB
    unsigned* s_sorted = (unsigned*)(sraw + 45056);           // 2048    =  8KB
    float*    s_val    = (float*)(sraw + 53248);              // 2048    =  8KB
    int*      s_hist   = (int*)(sraw + 61440);                // 256
    int*      s_off    = (int*)(sraw + 62464);                // NBINS+1
    unsigned* s_mask   = (unsigned*)(sraw + 63280);           // 32
    int*      s_wtot   = (int*)(sraw + 63412);                // 8
    int*      s_cnt    = (int*)(sraw + 63444);                // 2
    float*    s_tmin   = (float*)(sraw + 63452);              // 2
    float*    s_tmax   = (float*)(sraw + 63460);              // 2
    unsigned* s_max    = (unsigned*)(sraw + 63468);           // 2

    const int b    = blockIdx.x;
    const int tid  = threadIdx.x;
    const int lane = tid & 31;
    const int w    = tid >> 5;

    const float* __restrict__ row = inputs + (size_t)b * NGRID;

    // ---- A: indices (default caching -> L2-retained across replays) + ballots
    const int dm = dim_idx  [b * PPAIR + tid];
    const int bl = birth_loc[b * PPAIR + tid];
    const int dl = death_loc[b * PPAIR + tid];
    // prefetch first stream chunk early (independent of everything below)
    float4 r = *(const float4*)(row + 4 * tid);
    {
        unsigned mk1 = __ballot_sync(0xffffffffu, dm == 1);
        if (lane == 0) s_mask[w] = mk1;
    }
    if (tid < 256) s_hist[tid] = 0;
    if (tid < 2) s_max[tid] = 0u;
    __syncthreads();                                            // (1)

    // ---- S1: histogram locations by 1KB granule (loc>>8), 256 granules
    const int k1 = bl >> 8, k2 = dl >> 8;
    atomicAdd(&s_hist[k1], 1);
    atomicAdd(&s_hist[k2], 1);
    __syncthreads();                                            // (2)

    // ---- S2: exclusive prefix over 256 granules
    int pv = 0, piv = 0;
    if (tid < 256) {
        pv = s_hist[tid];
        piv = pv;
        #pragma unroll
        for (int o = 1; o < 32; o <<= 1) {
            int n = __shfl_up_sync(0xffffffffu, piv, o);
            if (lane >= o) piv += n;
        }
        if (lane == 31) s_wtot[w] = piv;
    }
    __syncthreads();                                            // (3)
    if (tid < 256) {
        int base = 0;
        #pragma unroll
        for (int q = 0; q < 8; q++) if (q < w) base += s_wtot[q];
        s_hist[tid] = piv - pv + base;       // granule start = scatter cursor
    }
    __syncthreads();                                            // (4)

    // ---- S3: scatter (loc<<16 | tag) into granule order; cursors become ENDs
    {
        int p1 = atomicAdd(&s_hist[k1], 1);
        s_sorted[p1] = ((unsigned)bl << 16) | (unsigned)(tid * 2);
        int p2 = atomicAdd(&s_hist[k2], 1);
        s_sorted[p2] = ((unsigned)dl << 16) | (unsigned)(tid * 2 + 1);
    }
    __syncthreads();                                            // (5)

    // ---- S4: stream the row coalesced; route needed values out of each chunk
    for (int c = 0; c < NCHUNK; c++) {
        // buf[c&1] is safe to overwrite (chunk c-2 consumers finished)
        *(float4*)(s_buf + (c & 1) * CHUNK + 4 * tid) = r;
        if (c + 1 < NCHUNK)
            r = *(const float4*)(row + (c + 1) * CHUNK + 4 * tid);
        __syncthreads();                    // chunk c staged
        const int lo = c ? s_hist[16 * c - 1] : 0;   // granule ends
        const int hi = s_hist[16 * c + 15];
        const float* bb = s_buf + (c & 1) * CHUNK - c * CHUNK;
        for (int i = lo + tid; i < hi; i += 1024) {
            unsigned e = s_sorted[i];
            s_val[e & 0x7FFu] = bb[e >> 16];
        }
        __syncthreads();                    // consumers of c done
    }
    if (tid < NBINS) s_hist[tid] = 0;       // re-zero for mid-bucket histogram
    __syncthreads();                                            // (6)

    const float vb = s_val[2 * tid];
    const float vd = s_val[2 * tid + 1];
    const float mid = 0.5f * (vb + vd);

    // ---- B: t-range from FIRST 2 valid pairs (bit-scan of ballot words)
    if (tid < 2) {
        const int dim = tid;
        float tmin = 1e30f, tmax = -1e30f;
        int found = 0, cnt = 0;
        #pragma unroll 4
        for (int ww = 0; ww < 32; ww++) {
            unsigned m = s_mask[ww];
            if (dim == 0) m = ~m;
            cnt += __popc(m);
            while (m && found < 2) {
                int l = __ffs(m) - 1; m &= m - 1;
                int p = ww * 32 + l;
                tmin = fminf(tmin, s_val[2 * p]);
                tmax = fmaxf(tmax, s_val[2 * p + 1]);
                found++;
            }
        }
        if (cnt == 0) { tmin = 0.0f; tmax = 0.0f; }
        s_cnt[dim] = cnt; s_tmin[dim] = tmin; s_tmax[dim] = tmax;
    }
    __syncthreads();                                            // (7)

    // ---- C: mid-bucket c = smallest j with tv_j >= mid; histogram
    int bin;
    {
        const float tmn  = s_tmin[dm], tmx = s_tmax[dm];
        const float num  = mid - tmn;
        const float step = (tmx - tmn) * (1.0f / (float)(TPTS - 1));
        int c;
        if (num <= 0.0f)       c = 0;
        else if (step <= 0.0f) c = NB - 1;
        else                   c = min(NB - 1, (int)ceilf(num / step));
        bin = dm * NB + c;
        atomicAdd(&s_hist[bin], 1);
    }
    __syncthreads();                                            // (8)

    // ---- D: exclusive prefix over 202 bins (7 warps)
    if (tid < 224) {
        int v = (tid < NBINS) ? s_hist[tid] : 0;
        int iv = v;
        #pragma unroll
        for (int o = 1; o < 32; o <<= 1) {
            int n = __shfl_up_sync(0xffffffffu, iv, o);
            if (lane >= o) iv += n;
        }
        if (lane == 31) s_wtot[w] = iv;
        s_off[tid] = iv - v;
    }
    __syncthreads();                                            // (9)
    if (tid < NBINS) {
        int base = 0;
        #pragma unroll
        for (int q = 0; q < 7; q++) if (q < w) base += s_wtot[q];
        int excl = s_off[tid] + base;
        s_off[tid] = excl;
        s_hist[tid] = excl;                  // scatter cursor
    }
    if (tid == 0) s_off[NBINS] = PPAIR;
    __syncthreads();                                            // (10)

    // ---- E: scatter (d, -b) bucket-contiguously
    {
        int pos = atomicAdd(&s_hist[bin], 1);
        s_pr[pos] = make_float2(vd, -vb);
    }
    __syncthreads();                                            // (11)

    // ---- F: per-bin top2 of d and of -b
    if (tid < NBINS) {
        const int dim = (tid >= NB), c = tid - dim * NB;
        const int st = s_off[tid], en = s_off[tid + 1];
        float d1 = SENT, d2 = SENT, n1 = SENT, n2 = SENT;
        for (int i = st; i < en; i++) {
            float2 e = s_pr[i];
            top2_upd(e.x, d1, d2);
            top2_upd(e.y, n1, n2);
        }
        s_scan[dim * 2 + 0][c] = make_float2(d1, d2);
        s_scan[dim * 2 + 1][c] = make_float2(n1, n2);
    }
    __syncthreads();                                            // (12)

    // ---- G: 4 warps, in-register top2 scan (side0 prefix asc, side1 suffix desc)
    if (w < 4) {
        const int side = w & 1;
        float2 rr[4];
        float2 acc = make_float2(SENT, SENT);
        #pragma unroll
        for (int k = 0; k < 4; k++) {
            int idx = lane * 4 + k;
            int j   = side ? 127 - idx : idx;
            float2 e = (j <= NB - 1) ? s_scan[w][j] : make_float2(SENT, SENT);
            acc = top2_merge(acc, e);
            rr[k] = acc;
        }
        float2 sc = acc;
        #pragma unroll
        for (int o = 1; o < 32; o <<= 1) {
            float2 ox;
            ox.x = __shfl_up_sync(0xffffffffu, sc.x, o);
            ox.y = __shfl_up_sync(0xffffffffu, sc.y, o);
            if (lane >= o) sc = top2_merge(sc, ox);
        }
        float2 ex;
        ex.x = __shfl_up_sync(0xffffffffu, sc.x, 1);
        ex.y = __shfl_up_sync(0xffffffffu, sc.y, 1);
        if (lane == 0) ex = make_float2(SENT, SENT);
        #pragma unroll
        for (int k = 0; k < 4; k++) {
            int idx = lane * 4 + k;
            int j   = side ? 127 - idx : idx;
            s_scan[w][j] = top2_merge(ex, rr[k]);
        }
    }
    __syncthreads();                                            // (13)

    // ---- H: finalize per (dim, t)
    if (tid < 256) {
        const int dim = tid >> 7;
        const int t   = tid & 127;
        float m1 = 0.0f;
        if (t < TPTS) {
            const float tmn = s_tmin[dim], tmx = s_tmax[dim];
            const float tv  = tmn + (tmx - tmn) * ((float)t * (1.0f / (float)(TPTS - 1)));
            float2 A  = s_scan[dim * 2 + 0][t];      // mids in buckets 0..t
            float2 Bs = s_scan[dim * 2 + 1][t + 1];  // mids in buckets t+1..
            float vA1 = A.x - tv,  vA2 = A.y - tv;   // d - tv
            float vB1 = Bs.x + tv, vB2 = Bs.y + tv;  // tv - b
            m1 = fmaxf(0.0f, fmaxf(vA1, vB1));
            float s2 = fmaxf(fminf(vA1, vB1), (vA1 >= vB1) ? vA2 : vB2);
            float m2 = fmaxf(0.0f, s2);
            *(float2*)&land[((size_t)(b * 2 + dim) * TPTS + t) * 2] =
                make_float2(m1, m2);
        }
        unsigned wm = __reduce_max_sync(0xffffffffu, __float_as_uint(m1));
        if (lane == 0) atomicMax(&s_max[dim], wm);  // m1 >= 0: bit order OK
    }
    __syncthreads();                                            // (14)

    if (tid < 2) {
        bool nz = (s_cnt[tid] > 0) && (__uint_as_float(s_max[tid]) > 0.0f);
        trange[b * 4 + 2 * tid + 0] = nz ? s_tmin[tid] : 0.0f;
        trange[b * 4 + 2 * tid + 1] = nz ? s_tmax[tid] : 0.0f;
    }
}

extern "C" void kernel_launch(void* const* d_in, const int* in_sizes, int n_in,
                              void* d_out, int out_size) {
    const float* inputs    = (const float*)d_in[0];
    const int*   dim_idx   = (const int*)  d_in[1];
    const int*   birth_loc = (const int*)  d_in[2];
    const int*   death_loc = (const int*)  d_in[3];

    float* land   = (float*)d_out;                        // B*2*T*2 = 102400
    float* trange = land + (size_t)BATCH * 2 * TPTS * 2;  // B*4     = 1024

    cudaFuncSetAttribute(pl_kernel,
                         cudaFuncAttributeMaxDynamicSharedMemorySize, SMEM_BYTES);
    pl_kernel<<<BATCH, 1024, SMEM_BYTES>>>(inputs, dim_idx, birth_loc, death_loc,
                                           land, trange);
}

// round 15
// speedup vs baseline: 1.1199x; 1.1199x over previous
#include <cuda_runtime.h>
#include <cuda_bf16.h>

#define BATCH 256
#define PPAIR 1024
#define TPTS  100
#define NGRID 65536
#define NB    (TPTS + 1)   // mid-buckets 0..100
#define NBINS (2 * NB)
#define SENT  (-1e30f)

__device__ float2 g_vals[BATCH * PPAIR];   // 2MB gather scratch

__device__ __forceinline__ void top2_upd(float v, float& a1, float& a2) {
    a2 = fmaxf(a2, fminf(a1, v));
    a1 = fmaxf(a1, v);
}
__device__ __forceinline__ float2 top2_merge(float2 a, float2 b) {
    float lo = fminf(a.x, b.x);
    return make_float2(fmaxf(a.x, b.x), fmaxf(lo, fmaxf(a.y, b.y)));
}

// ---------------- K1: barrier-free gather (1 pair / thread) ----------------
__global__ __launch_bounds__(256, 8)
void gather_kernel(const float* __restrict__ inputs,
                   const int*   __restrict__ birth_loc,
                   const int*   __restrict__ death_loc)
{
    const int idx = blockIdx.x * 256 + threadIdx.x;   // 0 .. B*P-1
    const int bl = __ldcs(birth_loc + idx);
    const int dl = __ldcs(death_loc + idx);
    const float* __restrict__ row = inputs + ((size_t)(idx >> 10) << 16);
    const float vb = __ldg(row + bl);
    const float vd = __ldg(row + dl);
    g_vals[idx] = make_float2(vb, vd);
}

// ---------------- K2: bucket + scan reduce (R9 structure, no gather) -------
__global__ __launch_bounds__(1024, 2)
void pl_kernel(const int* __restrict__ dim_idx,
               float* __restrict__ land,    // [B, 2, T, 2]
               float* __restrict__ trange)  // [B, 4]
{
    __shared__ float    s_val[2 * PPAIR];
    __shared__ unsigned s_mask[32];
    __shared__ __align__(16) float2 s_pr[PPAIR];
    __shared__ int      s_hist[NBINS];
    __shared__ int      s_off[NBINS + 1];
    __shared__ __align__(16) float2 s_scan[4][128];
    __shared__ int      s_wtot[7];
    __shared__ int      s_cnt[2];
    __shared__ float    s_tmin[2], s_tmax[2];
    __shared__ unsigned s_max[2];

    const int b    = blockIdx.x;
    const int tid  = threadIdx.x;
    const int lane = tid & 31;
    const int w    = tid >> 5;

    // ---- A: coalesced scratch read + dim ballots
    const int   dm = dim_idx[b * PPAIR + tid];
    const float2 v = g_vals[b * PPAIR + tid];
    const float vb = v.x, vd = v.y;
    *(float2*)&s_val[2 * tid] = v;
    {
        unsigned mk1 = __ballot_sync(0xffffffffu, dm == 1);
        if (lane == 0) s_mask[w] = mk1;
    }
    if (tid < NBINS) s_hist[tid] = 0;
    if (tid < 2) s_max[tid] = 0u;
    const float mid = 0.5f * (vb + vd);
    __syncthreads();                                            // (1)

    // ---- B: t-range from FIRST 2 valid pairs (bit-scan of ballot words)
    if (tid < 2) {
        const int dim = tid;
        float tmin = 1e30f, tmax = -1e30f;
        int found = 0, cnt = 0;
        #pragma unroll 4
        for (int ww = 0; ww < 32; ww++) {
            unsigned m = s_mask[ww];
            if (dim == 0) m = ~m;
            cnt += __popc(m);
            while (m && found < 2) {
                int l = __ffs(m) - 1; m &= m - 1;
                int p = ww * 32 + l;
                tmin = fminf(tmin, s_val[2 * p]);
                tmax = fmaxf(tmax, s_val[2 * p + 1]);
                found++;
            }
        }
        if (cnt == 0) { tmin = 0.0f; tmax = 0.0f; }
        s_cnt[dim] = cnt; s_tmin[dim] = tmin; s_tmax[dim] = tmax;
    }
    __syncthreads();                                            // (2)

    // ---- C: mid-bucket c = smallest j with tv_j >= mid; histogram
    int bin;
    {
        const float tmn  = s_tmin[dm], tmx = s_tmax[dm];
        const float num  = mid - tmn;
        const float step = (tmx - tmn) * (1.0f / (float)(TPTS - 1));
        int c;
        if (num <= 0.0f)       c = 0;
        else if (step <= 0.0f) c = NB - 1;
        else                   c = min(NB - 1, (int)ceilf(num / step));
        bin = dm * NB + c;
        atomicAdd(&s_hist[bin], 1);
    }
    __syncthreads();                                            // (3)

    // ---- D: exclusive prefix over 202 bins (7 warps)
    if (tid < 224) {
        int vv = (tid < NBINS) ? s_hist[tid] : 0;
        int iv = vv;
        #pragma unroll
        for (int o = 1; o < 32; o <<= 1) {
            int n = __shfl_up_sync(0xffffffffu, iv, o);
            if (lane >= o) iv += n;
        }
        if (lane == 31) s_wtot[w] = iv;
        s_off[tid] = iv - vv;
    }
    __syncthreads();                                            // (4)
    if (tid < NBINS) {
        int base = 0;
        #pragma unroll
        for (int q = 0; q < 7; q++) if (q < w) base += s_wtot[q];
        int excl = s_off[tid] + base;
        s_off[tid] = excl;
        s_hist[tid] = excl;                  // scatter cursor
    }
    if (tid == 0) s_off[NBINS] = PPAIR;
    __syncthreads();                                            // (5)

    // ---- E: scatter (d, -b) bucket-contiguously
    {
        int pos = atomicAdd(&s_hist[bin], 1);
        s_pr[pos] = make_float2(vd, -vb);
    }
    __syncthreads();                                            // (6)

    // ---- F: per-bin top2 of d and of -b
    if (tid < NBINS) {
        const int dim = (tid >= NB), c = tid - dim * NB;
        const int st = s_off[tid], en = s_off[tid + 1];
        float d1 = SENT, d2 = SENT, n1 = SENT, n2 = SENT;
        for (int i = st; i < en; i++) {
            float2 e = s_pr[i];
            top2_upd(e.x, d1, d2);
            top2_upd(e.y, n1, n2);
        }
        s_scan[dim * 2 + 0][c] = make_float2(d1, d2);
        s_scan[dim * 2 + 1][c] = make_float2(n1, n2);
    }
    __syncthreads();                                            // (7)

    // ---- G: 4 warps, in-register top2 scan (side0 prefix asc, side1 suffix desc)
    if (w < 4) {
        const int side = w & 1;
        float2 rr[4];
        float2 acc = make_float2(SENT, SENT);
        #pragma unroll
        for (int k = 0; k < 4; k++) {
            int idx = lane * 4 + k;
            int j   = side ? 127 - idx : idx;
            float2 e = (j <= NB - 1) ? s_scan[w][j] : make_float2(SENT, SENT);
            acc = top2_merge(acc, e);
            rr[k] = acc;
        }
        float2 sc = acc;
        #pragma unroll
        for (int o = 1; o < 32; o <<= 1) {
            float2 ox;
            ox.x = __shfl_up_sync(0xffffffffu, sc.x, o);
            ox.y = __shfl_up_sync(0xffffffffu, sc.y, o);
            if (lane >= o) sc = top2_merge(sc, ox);
        }
        float2 ex;
        ex.x = __shfl_up_sync(0xffffffffu, sc.x, 1);
        ex.y = __shfl_up_sync(0xffffffffu, sc.y, 1);
        if (lane == 0) ex = make_float2(SENT, SENT);
        #pragma unroll
        for (int k = 0; k < 4; k++) {
            int idx = lane * 4 + k;
            int j   = side ? 127 - idx : idx;
            s_scan[w][j] = top2_merge(ex, rr[k]);
        }
    }
    __syncthreads();                                            // (8)

    // ---- H: finalize per (dim, t)
    if (tid < 256) {
        const int dim = tid >> 7;
        const int t   = tid & 127;
        float m1 = 0.0f;
        if (t < TPTS) {
            const float tmn = s_tmin[dim], tmx = s_tmax[dim];
            const float tv  = tmn + (tmx - tmn) * ((float)t * (1.0f / (float)(TPTS - 1)));
            float2 A  = s_scan[dim * 2 + 0][t];      // mids in buckets 0..t
            float2 Bs = s_scan[dim * 2 + 1][t + 1];  // mids in buckets t+1..
            float vA1 = A.x - tv,  vA2 = A.y - tv;   // d - tv
            float vB1 = Bs.x + tv, vB2 = Bs.y + tv;  // tv - b
            m1 = fmaxf(0.0f, fmaxf(vA1, vB1));
            float s2 = fmaxf(fminf(vA1, vB1), (vA1 >= vB1) ? vA2 : vB2);
            float m2 = fmaxf(0.0f, s2);
            *(float2*)&land[((size_t)(b * 2 + dim) * TPTS + t) * 2] =
                make_float2(m1, m2);
        }
        unsigned wm = __reduce_max_sync(0xffffffffu, __float_as_uint(m1));
        if (lane == 0) atomicMax(&s_max[dim], wm);  // m1 >= 0: bit order OK
    }
    __syncthreads();                                            // (9)

    if (tid < 2) {
        bool nz = (s_cnt[tid] > 0) && (__uint_as_float(s_max[tid]) > 0.0f);
        trange[b * 4 + 2 * tid + 0] = nz ? s_tmin[tid] : 0.0f;
        trange[b * 4 + 2 * tid + 1] = nz ? s_tmax[tid] : 0.0f;
    }
}

extern "C" void kernel_launch(void* const* d_in, const int* in_sizes, int n_in,
                              void* d_out, int out_size) {
    const float* inputs    = (const float*)d_in[0];
    const int*   dim_idx   = (const int*)  d_in[1];
    const int*   birth_loc = (const int*)  d_in[2];
    const int*   death_loc = (const int*)  d_in[3];

    float* land   = (float*)d_out;                        // B*2*T*2 = 102400
    float* trange = land + (size_t)BATCH * 2 * TPTS * 2;  // B*4     = 1024

    gather_kernel<<<(BATCH * PPAIR) / 256, 256>>>(inputs, birth_loc, death_loc);
    pl_kernel<<<BATCH, 1024>>>(dim_idx, land, trange);
}

// round 16
// speedup vs baseline: 1.6617x; 1.4837x over previous
#include <cuda_runtime.h>
#include <cuda_bf16.h>

#define BATCH 256
#define PPAIR 1024
#define TPTS  100
#define NGRID 65536
#define NB    (TPTS + 1)   // mid-buckets 0..100
#define SENT  (-1e30f)

__device__ float2 g_vals[BATCH * PPAIR];   // 2MB gather scratch

// order-preserving float <-> uint (monotone: f1 < f2  <=>  enc(f1) < enc(f2))
__device__ __forceinline__ unsigned enc(float f) {
    unsigned u = __float_as_uint(f);
    return (u >> 31) ? ~u : (u | 0x80000000u);
}
__device__ __forceinline__ float dec(unsigned k) {
    return __uint_as_float((k & 0x80000000u) ? (k ^ 0x80000000u) : ~k);
}
__device__ __forceinline__ uint2 top2_merge(uint2 a, uint2 b) {
    unsigned lo = umin(a.x, b.x);
    return make_uint2(umax(a.x, b.x), umax(lo, umax(a.y, b.y)));
}

// ---------------- K1: barrier-free gather (1 pair / thread) ----------------
__global__ __launch_bounds__(256, 8)
void gather_kernel(const float* __restrict__ inputs,
                   const int*   __restrict__ birth_loc,
                   const int*   __restrict__ death_loc)
{
    const int idx = blockIdx.x * 256 + threadIdx.x;   // 0 .. B*P-1
    const int bl = __ldcs(birth_loc + idx);
    const int dl = __ldcs(death_loc + idx);
    const float* __restrict__ row = inputs + ((size_t)(idx >> 10) << 16);
    const float vb = __ldg(row + bl);
    const float vd = __ldg(row + dl);
    g_vals[idx] = make_float2(vb, vd);
}

// ---------------- K2: atomic-top2 + scan reduce ----------------------------
__global__ __launch_bounds__(1024, 2)
void pl_kernel(const int* __restrict__ dim_idx,
               float* __restrict__ land,    // [B, 2, T, 2]
               float* __restrict__ trange)  // [B, 4]
{
    __shared__ float    s_val[2 * PPAIR];
    __shared__ unsigned s_mask[32];
    __shared__ uint2    s_top[4][128];      // [dim*2+side][bucket] (M1,M2) keys
    __shared__ int      s_cnt[2];
    __shared__ float    s_tmin[2], s_tmax[2];
    __shared__ unsigned s_max[2];

    const int b    = blockIdx.x;
    const int tid  = threadIdx.x;
    const int lane = tid & 31;
    const int w    = tid >> 5;

    const unsigned K_SENT = enc(SENT);

    // ---- A: coalesced scratch read + dim ballots + init top2 arrays
    const int   dm = dim_idx[b * PPAIR + tid];
    const float2 v = g_vals[b * PPAIR + tid];
    const float vb = v.x, vd = v.y;
    *(float2*)&s_val[2 * tid] = v;
    {
        unsigned mk1 = __ballot_sync(0xffffffffu, dm == 1);
        if (lane == 0) s_mask[w] = mk1;
    }
    if (tid < 512) s_top[tid >> 7][tid & 127] = make_uint2(K_SENT, K_SENT);
    if (tid < 2) s_max[tid] = 0u;
    const float mid = 0.5f * (vb + vd);
    __syncthreads();                                            // (1)

    // ---- B: first-2 valid pairs, warp-parallel (warp0 -> dim0, warp1 -> dim1)
    if (w < 2) {
        unsigned m = s_mask[lane];
        if (w == 0) m = ~m;
        int c = __popc(m);
        int inc = c;
        #pragma unroll
        for (int o = 1; o < 32; o <<= 1) {
            int n = __shfl_up_sync(0xffffffffu, inc, o);
            if (lane >= o) inc += n;
        }
        const int cnt  = __shfl_sync(0xffffffffu, inc, 31);
        const int excl = inc - c;
        // locate global rank-0 and rank-1 set bits
        int p = -1;
        int r0 = 0 - excl, r1 = 1 - excl;
        if (r0 >= 0 && r0 < c) p = lane * 32 + (__fns(m, 0, r0 + 1));
        unsigned b0 = __ballot_sync(0xffffffffu, r0 >= 0 && r0 < c);
        int p0 = __shfl_sync(0xffffffffu, p, b0 ? (__ffs(b0) - 1) : 0);
        p = -1;
        if (r1 >= 0 && r1 < c) p = lane * 32 + (__fns(m, 0, r1 + 1));
        unsigned b1 = __ballot_sync(0xffffffffu, r1 >= 0 && r1 < c);
        int p1 = __shfl_sync(0xffffffffu, p, b1 ? (__ffs(b1) - 1) : 0);
        if (lane == 0) {
            float tmin = 0.0f, tmax = 0.0f;
            if (cnt > 0) {
                tmin = s_val[2 * p0];
                tmax = s_val[2 * p0 + 1];
                if (cnt > 1) {
                    tmin = fminf(tmin, s_val[2 * p1]);
                    tmax = fmaxf(tmax, s_val[2 * p1 + 1]);
                }
            }
            s_cnt[w] = cnt; s_tmin[w] = tmin; s_tmax[w] = tmax;
        }
    }
    __syncthreads();                                            // (2)

    // ---- C: bucket + atomic running top2 (exact: classic 2x atomicMax trick)
    {
        const float tmn  = s_tmin[dm], tmx = s_tmax[dm];
        const float num  = mid - tmn;
        const float step = (tmx - tmn) * (1.0f / (float)(TPTS - 1));
        int c;
        if (num <= 0.0f)       c = 0;
        else if (step <= 0.0f) c = NB - 1;
        else                   c = min(NB - 1, (int)ceilf(num / step));

        const unsigned kd = enc(vd);      // A side: death values
        const unsigned kb = enc(-vb);     // B side: -birth values
        uint2* A  = &s_top[dm * 2 + 0][c];
        uint2* Bs = &s_top[dm * 2 + 1][c];
        unsigned oldA = atomicMax(&A->x, kd);
        atomicMax(&A->y, umin(kd, oldA));
        unsigned oldB = atomicMax(&Bs->x, kb);
        atomicMax(&Bs->y, umin(kb, oldB));
    }
    __syncthreads();                                            // (3)

    // ---- G: 4 warps, in-register top2 scan (side0 prefix asc, side1 suffix desc)
    if (w < 4) {
        const int side = w & 1;
        uint2 rr[4];
        uint2 acc = make_uint2(K_SENT, K_SENT);
        #pragma unroll
        for (int k = 0; k < 4; k++) {
            int idx = lane * 4 + k;
            int j   = side ? 127 - idx : idx;
            uint2 e = (j <= NB - 1) ? s_top[w][j] : make_uint2(K_SENT, K_SENT);
            acc = top2_merge(acc, e);
            rr[k] = acc;
        }
        uint2 sc = acc;
        #pragma unroll
        for (int o = 1; o < 32; o <<= 1) {
            uint2 ox;
            ox.x = __shfl_up_sync(0xffffffffu, sc.x, o);
            ox.y = __shfl_up_sync(0xffffffffu, sc.y, o);
            if (lane >= o) sc = top2_merge(sc, ox);
        }
        uint2 ex;
        ex.x = __shfl_up_sync(0xffffffffu, sc.x, 1);
        ex.y = __shfl_up_sync(0xffffffffu, sc.y, 1);
        if (lane == 0) ex = make_uint2(K_SENT, K_SENT);
        #pragma unroll
        for (int k = 0; k < 4; k++) {
            int idx = lane * 4 + k;
            int j   = side ? 127 - idx : idx;
            s_top[w][j] = top2_merge(ex, rr[k]);   // in-place: own entries only
        }
    }
    __syncthreads();                                            // (4)

    // ---- H: finalize per (dim, t)
    if (tid < 256) {
        const int dim = tid >> 7;
        const int t   = tid & 127;
        float m1 = 0.0f;
        if (t < TPTS) {
            const float tmn = s_tmin[dim], tmx = s_tmax[dim];
            const float tv  = tmn + (tmx - tmn) * ((float)t * (1.0f / (float)(TPTS - 1)));
            uint2 A  = s_top[dim * 2 + 0][t];       // mids in buckets 0..t
            uint2 Bs = s_top[dim * 2 + 1][t + 1];   // mids in buckets t+1..
            float vA1 = dec(A.x) - tv,  vA2 = dec(A.y) - tv;   // d - tv
            float vB1 = dec(Bs.x) + tv, vB2 = dec(Bs.y) + tv;  // tv - b
            m1 = fmaxf(0.0f, fmaxf(vA1, vB1));
            float s2 = fmaxf(fminf(vA1, vB1), (vA1 >= vB1) ? vA2 : vB2);
            float m2 = fmaxf(0.0f, s2);
            *(float2*)&land[((size_t)(b * 2 + dim) * TPTS + t) * 2] =
                make_float2(m1, m2);
        }
        unsigned wm = __reduce_max_sync(0xffffffffu, __float_as_uint(m1));
        if (lane == 0) atomicMax(&s_max[dim], wm);  // m1 >= 0: bit order OK
    }
    __syncthreads();                                            // (5)

    if (tid < 2) {
        bool nz = (s_cnt[tid] > 0) && (__uint_as_float(s_max[tid]) > 0.0f);
        trange[b * 4 + 2 * tid + 0] = nz ? s_tmin[tid] : 0.0f;
        trange[b * 4 + 2 * tid + 1] = nz ? s_tmax[tid] : 0.0f;
    }
}

extern "C" void kernel_launch(void* const* d_in, const int* in_sizes, int n_in,
                              void* d_out, int out_size) {
    const float* inputs    = (const float*)d_in[0];
    const int*   dim_idx   = (const int*)  d_in[1];
    const int*   birth_loc = (const int*)  d_in[2];
    const int*   death_loc = (const int*)  d_in[3];

    float* land   = (float*)d_out;                        // B*2*T*2 = 102400
    float* trange = land + (size_t)BATCH * 2 * TPTS * 2;  // B*4     = 1024

    gather_kernel<<<(BATCH * PPAIR) / 256, 256>>>(inputs, birth_loc, death_loc);
    pl_kernel<<<BATCH, 1024>>>(dim_idx, land, trange);
}